// round 8
// baseline (speedup 1.0000x reference)
#include <cuda_runtime.h>
#include <stdint.h>

// TrafficGCN: 2-layer GCN, N=100000, E=3200000, HIDDEN=16.
// R7: single-pass pulls -- 16 lanes per node cover 64 CSR slots in one
// iteration (predicated int4 index loads + 4-wide predicated gathers, MLP=4).
// Kills the loop-carried idx->gather dependency and iteration imbalance seen
// in R6. CAP=64 (P(deg>64)~1e-7, exact overflow fallback kept).
//
// Inputs: d_in[0]=x f32[N,3], d_in[1]=edge_index i32[2,E],
//         d_in[2]=W1 f32[3,16], d_in[3]=b1 f32[16], d_in[4]=W2 f32[16,1],
//         d_in[5]=b2 f32[1].  Output: f32[N].

#define MAXN 100608
#define HID 16
#define CAP 64
#define OVF_CAP 65536

__device__ int    g_cnt[MAXN];
__device__ int    g_csr[(size_t)MAXN * CAP];
__device__ int    g_ovf_cnt;
__device__ int2   g_ovf[OVF_CAP];
__device__ float  g_isd[MAXN];
__device__ float4 g_px[MAXN];    // isd[i]*x[i] (w unused)
__device__ float  g_p[MAXN];     // isd[i]*g[i]

// ---------------------------------------------------------------------------
__global__ void k_zero(int n) {
    int i = blockIdx.x * blockDim.x + threadIdx.x;
    if (i < n) g_cnt[i] = 0;
    if (i == 0) g_ovf_cnt = 0;
}

__device__ __forceinline__ void build_one(int s, int d) {
    int slot = atomicAdd(&g_cnt[d], 1);
    if (slot < CAP) {
        g_csr[(size_t)d * CAP + slot] = s;
    } else {
        int o = atomicAdd(&g_ovf_cnt, 1);
        if (o < OVF_CAP) g_ovf[o] = make_int2(s, d);
    }
}

// Build CSR, 8 edges/thread
__global__ void k_build8(const int* __restrict__ src,
                         const int* __restrict__ dst, int E8) {
    int t = blockIdx.x * blockDim.x + threadIdx.x;
    if (t >= E8) return;
    int4 s0 = ((const int4*)src)[2 * t];
    int4 s1 = ((const int4*)src)[2 * t + 1];
    int4 d0 = ((const int4*)dst)[2 * t];
    int4 d1 = ((const int4*)dst)[2 * t + 1];
    build_one(s0.x, d0.x); build_one(s0.y, d0.y);
    build_one(s0.z, d0.z); build_one(s0.w, d0.w);
    build_one(s1.x, d1.x); build_one(s1.y, d1.y);
    build_one(s1.z, d1.z); build_one(s1.w, d1.w);
}
__global__ void k_build1(const int* __restrict__ src,
                         const int* __restrict__ dst, int base, int E) {
    int e = base + blockIdx.x * blockDim.x + threadIdx.x;
    if (e < E) build_one(src[e], dst[e]);
}

// Per-node: isd = rsqrt(deg+1); px = isd * x
__global__ void k_node1(const float* __restrict__ x, int n) {
    int i = blockIdx.x * blockDim.x + threadIdx.x;
    if (i >= n) return;
    float isd = rsqrtf((float)(g_cnt[i] + 1));
    g_isd[i] = isd;
    g_px[i] = make_float4(isd * x[3*i+0], isd * x[3*i+1], isd * x[3*i+2], 0.f);
}

// Layer-1 pull + fused MLP. 16 lanes/node, 2 nodes/warp, single pass.
// Lane j owns slots 4j..4j+3 and hidden unit c=j.
__global__ void k_pull1(const float* __restrict__ W1,
                        const float* __restrict__ b1,
                        const float* __restrict__ W2, int n) {
    int gid  = blockIdx.x * blockDim.x + threadIdx.x;
    int lane = threadIdx.x & 31;
    int j    = lane & 15;
    int d    = gid >> 4;
    unsigned gmask = 0xFFFFu << (lane & 16);

    float w0 = __ldg(&W1[j]);
    float w1 = __ldg(&W1[HID + j]);
    float w2 = __ldg(&W1[2*HID + j]);
    float bb = __ldg(&b1[j]);
    float v2 = __ldg(&W2[j]);

    if (d >= n) return;
    int cnt = g_cnt[d];
    int m = min(cnt, CAP);
    const int4* row4 = (const int4*)(g_csr + (size_t)d * CAP);

    float ax, ay, az;
    if (j == 0) { float4 sv = __ldg(&g_px[d]); ax = sv.x; ay = sv.y; az = sv.z; }
    else        { ax = 0.f; ay = 0.f; az = 0.f; }

    int sl = 4 * j;
    if (sl < m) {
        int4 idx = __ldg(&row4[j]);
        { float4 v = __ldg(&g_px[idx.x]); ax += v.x; ay += v.y; az += v.z; }
        if (sl + 1 < m) { float4 v = __ldg(&g_px[idx.y]); ax += v.x; ay += v.y; az += v.z; }
        if (sl + 2 < m) { float4 v = __ldg(&g_px[idx.z]); ax += v.x; ay += v.y; az += v.z; }
        if (sl + 3 < m) { float4 v = __ldg(&g_px[idx.w]); ax += v.x; ay += v.y; az += v.z; }
    }
    // Exact overflow fallback (essentially never taken: P(deg>64)~1e-7)
    int ovn = g_ovf_cnt;
    if (ovn > 0) {
        for (int t = j; t < ovn; t += 16) {
            int2 e = g_ovf[t];
            if (e.y == d) {
                float4 v = __ldg(&g_px[e.x]);
                ax += v.x; ay += v.y; az += v.z;
            }
        }
    }
#pragma unroll
    for (int o = 8; o; o >>= 1) {
        ax += __shfl_xor_sync(gmask, ax, o);
        ay += __shfl_xor_sync(gmask, ay, o);
        az += __shfl_xor_sync(gmask, az, o);
    }
    float isd = g_isd[d];
    float f0 = isd * ax, f1 = isd * ay, f2 = isd * az;

    float h  = fmaxf(f0 * w0 + f1 * w1 + f2 * w2 + bb, 0.f);
    float ps = h * v2;
#pragma unroll
    for (int o = 8; o; o >>= 1) ps += __shfl_xor_sync(gmask, ps, o);
    if (j == 0) g_p[d] = isd * ps;
}

// Layer-2 pull + final. 16 lanes/node, single pass, scalar gathers.
__global__ void k_pull2(const float* __restrict__ b2,
                        float* __restrict__ out, int n) {
    int gid  = blockIdx.x * blockDim.x + threadIdx.x;
    int lane = threadIdx.x & 31;
    int j    = lane & 15;
    int d    = gid >> 4;
    unsigned gmask = 0xFFFFu << (lane & 16);
    if (d >= n) return;
    int m = min(g_cnt[d], CAP);
    const int4* row4 = (const int4*)(g_csr + (size_t)d * CAP);

    float a = (j == 0) ? __ldg(&g_p[d]) : 0.f;   // self-loop
    int sl = 4 * j;
    if (sl < m) {
        int4 idx = __ldg(&row4[j]);
        a += __ldg(&g_p[idx.x]);
        if (sl + 1 < m) a += __ldg(&g_p[idx.y]);
        if (sl + 2 < m) a += __ldg(&g_p[idx.z]);
        if (sl + 3 < m) a += __ldg(&g_p[idx.w]);
    }
    int ovn = g_ovf_cnt;
    if (ovn > 0) {
        for (int t = j; t < ovn; t += 16) {
            int2 e = g_ovf[t];
            if (e.y == d) a += __ldg(&g_p[e.x]);
        }
    }
#pragma unroll
    for (int o = 8; o; o >>= 1) a += __shfl_xor_sync(gmask, a, o);
    if (j == 0) out[d] = __ldg(&b2[0]) + g_isd[d] * a;
}

// ---------------------------------------------------------------------------
extern "C" void kernel_launch(void* const* d_in, const int* in_sizes, int n_in,
                              void* d_out, int out_size) {
    const float* x  = (const float*)d_in[0];
    const int*   ei = (const int*)  d_in[1];
    const float* W1 = (const float*)d_in[2];
    const float* b1 = (const float*)d_in[3];
    const float* W2 = (const float*)d_in[4];
    const float* b2 = (const float*)d_in[5];
    float* out = (float*)d_out;

    int n = in_sizes[0] / 3;
    int E = in_sizes[1] / 2;
    const int* src = ei;
    const int* dst = ei + E;

    const int T = 256;
    int nb_n = (n + T - 1) / T;

    int E8   = E / 8;
    int rem  = E - E8 * 8;
    int base = E8 * 8;
    int nb_e8 = (E8 + T - 1) / T;

    long long pull_threads = 16LL * n;
    int nb_p = (int)((pull_threads + T - 1) / T);

    k_zero  <<<nb_n, T>>>(n);
    k_build8<<<nb_e8, T>>>(src, dst, E8);
    if (rem) k_build1<<<(rem + T - 1) / T, T>>>(src, dst, base, E);
    k_node1 <<<nb_n, T>>>(x, n);
    k_pull1 <<<nb_p, T>>>(W1, b1, W2, n);
    k_pull2 <<<nb_p, T>>>(b2, out, n);
}

// round 11
// speedup vs baseline: 1.0159x; 1.0159x over previous
#include <cuda_runtime.h>
#include <stdint.h>

// TrafficGCN: 2-layer GCN, N=100000, E=3200000, HIDDEN=16.
// R8: CSR pull, 8 lanes/node (4 nodes/warp) with BOTH int4 index quads
// prefetched up front (covers 64 slots, no loop, no carried dependency),
// then up to 8 predicated gathers per lane (MLP<=8). CAP=64 + exact
// overflow fallback. Build kernel unchanged (at its atomic floor).
//
// Inputs: d_in[0]=x f32[N,3], d_in[1]=edge_index i32[2,E],
//         d_in[2]=W1 f32[3,16], d_in[3]=b1 f32[16], d_in[4]=W2 f32[16,1],
//         d_in[5]=b2 f32[1].  Output: f32[N].

#define MAXN 100608
#define HID 16
#define CAP 64
#define OVF_CAP 65536

__device__ int    g_cnt[MAXN];
__device__ int    g_csr[(size_t)MAXN * CAP];
__device__ int    g_ovf_cnt;
__device__ int2   g_ovf[OVF_CAP];
__device__ float  g_isd[MAXN];
__device__ float4 g_px[MAXN];    // isd[i]*x[i] (w unused)
__device__ float  g_p[MAXN];     // isd[i]*g[i]

// ---------------------------------------------------------------------------
__global__ void k_zero(int n) {
    int i = blockIdx.x * blockDim.x + threadIdx.x;
    if (i < n) g_cnt[i] = 0;
    if (i == 0) g_ovf_cnt = 0;
}

__device__ __forceinline__ void build_one(int s, int d) {
    int slot = atomicAdd(&g_cnt[d], 1);
    if (slot < CAP) {
        g_csr[(size_t)d * CAP + slot] = s;
    } else {
        int o = atomicAdd(&g_ovf_cnt, 1);
        if (o < OVF_CAP) g_ovf[o] = make_int2(s, d);
    }
}

// Build CSR, 8 edges/thread
__global__ void k_build8(const int* __restrict__ src,
                         const int* __restrict__ dst, int E8) {
    int t = blockIdx.x * blockDim.x + threadIdx.x;
    if (t >= E8) return;
    int4 s0 = ((const int4*)src)[2 * t];
    int4 s1 = ((const int4*)src)[2 * t + 1];
    int4 d0 = ((const int4*)dst)[2 * t];
    int4 d1 = ((const int4*)dst)[2 * t + 1];
    build_one(s0.x, d0.x); build_one(s0.y, d0.y);
    build_one(s0.z, d0.z); build_one(s0.w, d0.w);
    build_one(s1.x, d1.x); build_one(s1.y, d1.y);
    build_one(s1.z, d1.z); build_one(s1.w, d1.w);
}
__global__ void k_build1(const int* __restrict__ src,
                         const int* __restrict__ dst, int base, int E) {
    int e = base + blockIdx.x * blockDim.x + threadIdx.x;
    if (e < E) build_one(src[e], dst[e]);
}

// Per-node: isd = rsqrt(deg+1); px = isd * x
__global__ void k_node1(const float* __restrict__ x, int n) {
    int i = blockIdx.x * blockDim.x + threadIdx.x;
    if (i >= n) return;
    float isd = rsqrtf((float)(g_cnt[i] + 1));
    g_isd[i] = isd;
    g_px[i] = make_float4(isd * x[3*i+0], isd * x[3*i+1], isd * x[3*i+2], 0.f);
}

// Layer-1 pull + fused MLP. 8 lanes/node, 4 nodes/warp.
// Lane j prefetches index quads at slots [4j,4j+3] and [32+4j,32+4j+3],
// then up to 8 predicated gathers. Hidden units c=j and c=j+8 per lane.
__global__ void k_pull1(const float* __restrict__ W1,
                        const float* __restrict__ b1,
                        const float* __restrict__ W2, int n) {
    int gid  = blockIdx.x * blockDim.x + threadIdx.x;
    int lane = threadIdx.x & 31;
    int j    = lane & 7;
    int d    = gid >> 3;
    unsigned gmask = 0xFFu << (lane & 24);

    int c0 = j, c1 = j + 8;
    float w00 = __ldg(&W1[c0]),          w01 = __ldg(&W1[c1]);
    float w10 = __ldg(&W1[HID + c0]),    w11 = __ldg(&W1[HID + c1]);
    float w20 = __ldg(&W1[2*HID + c0]),  w21 = __ldg(&W1[2*HID + c1]);
    float bb0 = __ldg(&b1[c0]),          bb1 = __ldg(&b1[c1]);
    float v20 = __ldg(&W2[c0]),          v21 = __ldg(&W2[c1]);

    if (d >= n) return;
    int m = min(g_cnt[d], CAP);
    const int4* row4 = (const int4*)(g_csr + (size_t)d * CAP);

    int sA = 4 * j;          // slots sA..sA+3   (quad j)
    int sB = 32 + 4 * j;     // slots sB..sB+3   (quad j+8)
    int4 iA, iB;
    if (sA < m) iA = __ldg(&row4[j]);
    if (sB < m) iB = __ldg(&row4[j + 8]);

    float ax, ay, az;
    if (j == 0) { float4 sv = __ldg(&g_px[d]); ax = sv.x; ay = sv.y; az = sv.z; }
    else        { ax = 0.f; ay = 0.f; az = 0.f; }

    if (sA < m) {
        { float4 v = __ldg(&g_px[iA.x]); ax += v.x; ay += v.y; az += v.z; }
        if (sA + 1 < m) { float4 v = __ldg(&g_px[iA.y]); ax += v.x; ay += v.y; az += v.z; }
        if (sA + 2 < m) { float4 v = __ldg(&g_px[iA.z]); ax += v.x; ay += v.y; az += v.z; }
        if (sA + 3 < m) { float4 v = __ldg(&g_px[iA.w]); ax += v.x; ay += v.y; az += v.z; }
    }
    if (sB < m) {
        { float4 v = __ldg(&g_px[iB.x]); ax += v.x; ay += v.y; az += v.z; }
        if (sB + 1 < m) { float4 v = __ldg(&g_px[iB.y]); ax += v.x; ay += v.y; az += v.z; }
        if (sB + 2 < m) { float4 v = __ldg(&g_px[iB.z]); ax += v.x; ay += v.y; az += v.z; }
        if (sB + 3 < m) { float4 v = __ldg(&g_px[iB.w]); ax += v.x; ay += v.y; az += v.z; }
    }
    int ovn = g_ovf_cnt;
    if (ovn > 0) {
        for (int t = j; t < ovn; t += 8) {
            int2 e = g_ovf[t];
            if (e.y == d) {
                float4 v = __ldg(&g_px[e.x]);
                ax += v.x; ay += v.y; az += v.z;
            }
        }
    }
#pragma unroll
    for (int o = 4; o; o >>= 1) {
        ax += __shfl_xor_sync(gmask, ax, o);
        ay += __shfl_xor_sync(gmask, ay, o);
        az += __shfl_xor_sync(gmask, az, o);
    }
    float isd = g_isd[d];
    float f0 = isd * ax, f1 = isd * ay, f2 = isd * az;

    float h0 = fmaxf(f0 * w00 + f1 * w10 + f2 * w20 + bb0, 0.f);
    float h1 = fmaxf(f0 * w01 + f1 * w11 + f2 * w21 + bb1, 0.f);
    float ps = h0 * v20 + h1 * v21;
#pragma unroll
    for (int o = 4; o; o >>= 1) ps += __shfl_xor_sync(gmask, ps, o);
    if (j == 0) g_p[d] = isd * ps;
}

// Layer-2 pull + final. Same dual-prefetch structure, scalar gathers.
__global__ void k_pull2(const float* __restrict__ b2,
                        float* __restrict__ out, int n) {
    int gid  = blockIdx.x * blockDim.x + threadIdx.x;
    int lane = threadIdx.x & 31;
    int j    = lane & 7;
    int d    = gid >> 3;
    unsigned gmask = 0xFFu << (lane & 24);
    if (d >= n) return;
    int m = min(g_cnt[d], CAP);
    const int4* row4 = (const int4*)(g_csr + (size_t)d * CAP);

    int sA = 4 * j;
    int sB = 32 + 4 * j;
    int4 iA, iB;
    if (sA < m) iA = __ldg(&row4[j]);
    if (sB < m) iB = __ldg(&row4[j + 8]);

    float a = (j == 0) ? __ldg(&g_p[d]) : 0.f;   // self-loop
    if (sA < m) {
        a += __ldg(&g_p[iA.x]);
        if (sA + 1 < m) a += __ldg(&g_p[iA.y]);
        if (sA + 2 < m) a += __ldg(&g_p[iA.z]);
        if (sA + 3 < m) a += __ldg(&g_p[iA.w]);
    }
    if (sB < m) {
        a += __ldg(&g_p[iB.x]);
        if (sB + 1 < m) a += __ldg(&g_p[iB.y]);
        if (sB + 2 < m) a += __ldg(&g_p[iB.z]);
        if (sB + 3 < m) a += __ldg(&g_p[iB.w]);
    }
    int ovn = g_ovf_cnt;
    if (ovn > 0) {
        for (int t = j; t < ovn; t += 8) {
            int2 e = g_ovf[t];
            if (e.y == d) a += __ldg(&g_p[e.x]);
        }
    }
#pragma unroll
    for (int o = 4; o; o >>= 1) a += __shfl_xor_sync(gmask, a, o);
    if (j == 0) out[d] = __ldg(&b2[0]) + g_isd[d] * a;
}

// ---------------------------------------------------------------------------
extern "C" void kernel_launch(void* const* d_in, const int* in_sizes, int n_in,
                              void* d_out, int out_size) {
    const float* x  = (const float*)d_in[0];
    const int*   ei = (const int*)  d_in[1];
    const float* W1 = (const float*)d_in[2];
    const float* b1 = (const float*)d_in[3];
    const float* W2 = (const float*)d_in[4];
    const float* b2 = (const float*)d_in[5];
    float* out = (float*)d_out;

    int n = in_sizes[0] / 3;
    int E = in_sizes[1] / 2;
    const int* src = ei;
    const int* dst = ei + E;

    const int T = 256;
    int nb_n = (n + T - 1) / T;

    int E8   = E / 8;
    int rem  = E - E8 * 8;
    int base = E8 * 8;
    int nb_e8 = (E8 + T - 1) / T;

    long long pull_threads = 8LL * n;
    int nb_p = (int)((pull_threads + T - 1) / T);

    k_zero  <<<nb_n, T>>>(n);
    k_build8<<<nb_e8, T>>>(src, dst, E8);
    if (rem) k_build1<<<(rem + T - 1) / T, T>>>(src, dst, base, E);
    k_node1 <<<nb_n, T>>>(x, n);
    k_pull1 <<<nb_p, T>>>(W1, b1, W2, n);
    k_pull2 <<<nb_p, T>>>(b2, out, n);
}

// round 12
// speedup vs baseline: 1.0214x; 1.0053x over previous
#include <cuda_runtime.h>
#include <stdint.h>

// TrafficGCN: 2-layer GCN, N=100000, E=3200000, HIDDEN=16.
// R8: CSR pull, 8 lanes/node (4 nodes/warp) with BOTH int4 index quads
// prefetched up front (covers 64 slots, no loop, no carried dependency),
// then up to 8 predicated gathers per lane (MLP<=8). CAP=64 + exact
// overflow fallback. Build kernel unchanged (at its atomic floor).
//
// Inputs: d_in[0]=x f32[N,3], d_in[1]=edge_index i32[2,E],
//         d_in[2]=W1 f32[3,16], d_in[3]=b1 f32[16], d_in[4]=W2 f32[16,1],
//         d_in[5]=b2 f32[1].  Output: f32[N].

#define MAXN 100608
#define HID 16
#define CAP 64
#define OVF_CAP 65536

__device__ int    g_cnt[MAXN];
__device__ int    g_csr[(size_t)MAXN * CAP];
__device__ int    g_ovf_cnt;
__device__ int2   g_ovf[OVF_CAP];
__device__ float  g_isd[MAXN];
__device__ float4 g_px[MAXN];    // isd[i]*x[i] (w unused)
__device__ float  g_p[MAXN];     // isd[i]*g[i]

// ---------------------------------------------------------------------------
__global__ void k_zero(int n) {
    int i = blockIdx.x * blockDim.x + threadIdx.x;
    if (i < n) g_cnt[i] = 0;
    if (i == 0) g_ovf_cnt = 0;
}

__device__ __forceinline__ void build_one(int s, int d) {
    int slot = atomicAdd(&g_cnt[d], 1);
    if (slot < CAP) {
        g_csr[(size_t)d * CAP + slot] = s;
    } else {
        int o = atomicAdd(&g_ovf_cnt, 1);
        if (o < OVF_CAP) g_ovf[o] = make_int2(s, d);
    }
}

// Build CSR, 8 edges/thread
__global__ void k_build8(const int* __restrict__ src,
                         const int* __restrict__ dst, int E8) {
    int t = blockIdx.x * blockDim.x + threadIdx.x;
    if (t >= E8) return;
    int4 s0 = ((const int4*)src)[2 * t];
    int4 s1 = ((const int4*)src)[2 * t + 1];
    int4 d0 = ((const int4*)dst)[2 * t];
    int4 d1 = ((const int4*)dst)[2 * t + 1];
    build_one(s0.x, d0.x); build_one(s0.y, d0.y);
    build_one(s0.z, d0.z); build_one(s0.w, d0.w);
    build_one(s1.x, d1.x); build_one(s1.y, d1.y);
    build_one(s1.z, d1.z); build_one(s1.w, d1.w);
}
__global__ void k_build1(const int* __restrict__ src,
                         const int* __restrict__ dst, int base, int E) {
    int e = base + blockIdx.x * blockDim.x + threadIdx.x;
    if (e < E) build_one(src[e], dst[e]);
}

// Per-node: isd = rsqrt(deg+1); px = isd * x
__global__ void k_node1(const float* __restrict__ x, int n) {
    int i = blockIdx.x * blockDim.x + threadIdx.x;
    if (i >= n) return;
    float isd = rsqrtf((float)(g_cnt[i] + 1));
    g_isd[i] = isd;
    g_px[i] = make_float4(isd * x[3*i+0], isd * x[3*i+1], isd * x[3*i+2], 0.f);
}

// Layer-1 pull + fused MLP. 8 lanes/node, 4 nodes/warp.
// Lane j prefetches index quads at slots [4j,4j+3] and [32+4j,32+4j+3],
// then up to 8 predicated gathers. Hidden units c=j and c=j+8 per lane.
__global__ void k_pull1(const float* __restrict__ W1,
                        const float* __restrict__ b1,
                        const float* __restrict__ W2, int n) {
    int gid  = blockIdx.x * blockDim.x + threadIdx.x;
    int lane = threadIdx.x & 31;
    int j    = lane & 7;
    int d    = gid >> 3;
    unsigned gmask = 0xFFu << (lane & 24);

    int c0 = j, c1 = j + 8;
    float w00 = __ldg(&W1[c0]),          w01 = __ldg(&W1[c1]);
    float w10 = __ldg(&W1[HID + c0]),    w11 = __ldg(&W1[HID + c1]);
    float w20 = __ldg(&W1[2*HID + c0]),  w21 = __ldg(&W1[2*HID + c1]);
    float bb0 = __ldg(&b1[c0]),          bb1 = __ldg(&b1[c1]);
    float v20 = __ldg(&W2[c0]),          v21 = __ldg(&W2[c1]);

    if (d >= n) return;
    int m = min(g_cnt[d], CAP);
    const int4* row4 = (const int4*)(g_csr + (size_t)d * CAP);

    int sA = 4 * j;          // slots sA..sA+3   (quad j)
    int sB = 32 + 4 * j;     // slots sB..sB+3   (quad j+8)
    int4 iA, iB;
    if (sA < m) iA = __ldg(&row4[j]);
    if (sB < m) iB = __ldg(&row4[j + 8]);

    float ax, ay, az;
    if (j == 0) { float4 sv = __ldg(&g_px[d]); ax = sv.x; ay = sv.y; az = sv.z; }
    else        { ax = 0.f; ay = 0.f; az = 0.f; }

    if (sA < m) {
        { float4 v = __ldg(&g_px[iA.x]); ax += v.x; ay += v.y; az += v.z; }
        if (sA + 1 < m) { float4 v = __ldg(&g_px[iA.y]); ax += v.x; ay += v.y; az += v.z; }
        if (sA + 2 < m) { float4 v = __ldg(&g_px[iA.z]); ax += v.x; ay += v.y; az += v.z; }
        if (sA + 3 < m) { float4 v = __ldg(&g_px[iA.w]); ax += v.x; ay += v.y; az += v.z; }
    }
    if (sB < m) {
        { float4 v = __ldg(&g_px[iB.x]); ax += v.x; ay += v.y; az += v.z; }
        if (sB + 1 < m) { float4 v = __ldg(&g_px[iB.y]); ax += v.x; ay += v.y; az += v.z; }
        if (sB + 2 < m) { float4 v = __ldg(&g_px[iB.z]); ax += v.x; ay += v.y; az += v.z; }
        if (sB + 3 < m) { float4 v = __ldg(&g_px[iB.w]); ax += v.x; ay += v.y; az += v.z; }
    }
    int ovn = g_ovf_cnt;
    if (ovn > 0) {
        for (int t = j; t < ovn; t += 8) {
            int2 e = g_ovf[t];
            if (e.y == d) {
                float4 v = __ldg(&g_px[e.x]);
                ax += v.x; ay += v.y; az += v.z;
            }
        }
    }
#pragma unroll
    for (int o = 4; o; o >>= 1) {
        ax += __shfl_xor_sync(gmask, ax, o);
        ay += __shfl_xor_sync(gmask, ay, o);
        az += __shfl_xor_sync(gmask, az, o);
    }
    float isd = g_isd[d];
    float f0 = isd * ax, f1 = isd * ay, f2 = isd * az;

    float h0 = fmaxf(f0 * w00 + f1 * w10 + f2 * w20 + bb0, 0.f);
    float h1 = fmaxf(f0 * w01 + f1 * w11 + f2 * w21 + bb1, 0.f);
    float ps = h0 * v20 + h1 * v21;
#pragma unroll
    for (int o = 4; o; o >>= 1) ps += __shfl_xor_sync(gmask, ps, o);
    if (j == 0) g_p[d] = isd * ps;
}

// Layer-2 pull + final. Same dual-prefetch structure, scalar gathers.
__global__ void k_pull2(const float* __restrict__ b2,
                        float* __restrict__ out, int n) {
    int gid  = blockIdx.x * blockDim.x + threadIdx.x;
    int lane = threadIdx.x & 31;
    int j    = lane & 7;
    int d    = gid >> 3;
    unsigned gmask = 0xFFu << (lane & 24);
    if (d >= n) return;
    int m = min(g_cnt[d], CAP);
    const int4* row4 = (const int4*)(g_csr + (size_t)d * CAP);

    int sA = 4 * j;
    int sB = 32 + 4 * j;
    int4 iA, iB;
    if (sA < m) iA = __ldg(&row4[j]);
    if (sB < m) iB = __ldg(&row4[j + 8]);

    float a = (j == 0) ? __ldg(&g_p[d]) : 0.f;   // self-loop
    if (sA < m) {
        a += __ldg(&g_p[iA.x]);
        if (sA + 1 < m) a += __ldg(&g_p[iA.y]);
        if (sA + 2 < m) a += __ldg(&g_p[iA.z]);
        if (sA + 3 < m) a += __ldg(&g_p[iA.w]);
    }
    if (sB < m) {
        a += __ldg(&g_p[iB.x]);
        if (sB + 1 < m) a += __ldg(&g_p[iB.y]);
        if (sB + 2 < m) a += __ldg(&g_p[iB.z]);
        if (sB + 3 < m) a += __ldg(&g_p[iB.w]);
    }
    int ovn = g_ovf_cnt;
    if (ovn > 0) {
        for (int t = j; t < ovn; t += 8) {
            int2 e = g_ovf[t];
            if (e.y == d) a += __ldg(&g_p[e.x]);
        }
    }
#pragma unroll
    for (int o = 4; o; o >>= 1) a += __shfl_xor_sync(gmask, a, o);
    if (j == 0) out[d] = __ldg(&b2[0]) + g_isd[d] * a;
}

// ---------------------------------------------------------------------------
extern "C" void kernel_launch(void* const* d_in, const int* in_sizes, int n_in,
                              void* d_out, int out_size) {
    const float* x  = (const float*)d_in[0];
    const int*   ei = (const int*)  d_in[1];
    const float* W1 = (const float*)d_in[2];
    const float* b1 = (const float*)d_in[3];
    const float* W2 = (const float*)d_in[4];
    const float* b2 = (const float*)d_in[5];
    float* out = (float*)d_out;

    int n = in_sizes[0] / 3;
    int E = in_sizes[1] / 2;
    const int* src = ei;
    const int* dst = ei + E;

    const int T = 256;
    int nb_n = (n + T - 1) / T;

    int E8   = E / 8;
    int rem  = E - E8 * 8;
    int base = E8 * 8;
    int nb_e8 = (E8 + T - 1) / T;

    long long pull_threads = 8LL * n;
    int nb_p = (int)((pull_threads + T - 1) / T);

    k_zero  <<<nb_n, T>>>(n);
    k_build8<<<nb_e8, T>>>(src, dst, E8);
    if (rem) k_build1<<<(rem + T - 1) / T, T>>>(src, dst, base, E);
    k_node1 <<<nb_n, T>>>(x, n);
    k_pull1 <<<nb_p, T>>>(W1, b1, W2, n);
    k_pull2 <<<nb_p, T>>>(b2, out, n);
}

// round 13
// speedup vs baseline: 1.0467x; 1.0248x over previous
#include <cuda_runtime.h>
#include <stdint.h>

// TrafficGCN: 2-layer GCN, N=100000, E=3200000, HIDDEN=16.
// R8: CSR pull, 8 lanes/node (4 nodes/warp) with BOTH int4 index quads
// prefetched up front (covers 64 slots, no loop, no carried dependency),
// then up to 8 predicated gathers per lane (MLP<=8). CAP=64 + exact
// overflow fallback. Build kernel unchanged (at its atomic floor).
//
// Inputs: d_in[0]=x f32[N,3], d_in[1]=edge_index i32[2,E],
//         d_in[2]=W1 f32[3,16], d_in[3]=b1 f32[16], d_in[4]=W2 f32[16,1],
//         d_in[5]=b2 f32[1].  Output: f32[N].

#define MAXN 100608
#define HID 16
#define CAP 64
#define OVF_CAP 65536

__device__ int    g_cnt[MAXN];
__device__ int    g_csr[(size_t)MAXN * CAP];
__device__ int    g_ovf_cnt;
__device__ int2   g_ovf[OVF_CAP];
__device__ float  g_isd[MAXN];
__device__ float4 g_px[MAXN];    // isd[i]*x[i] (w unused)
__device__ float  g_p[MAXN];     // isd[i]*g[i]

// ---------------------------------------------------------------------------
__global__ void k_zero(int n) {
    int i = blockIdx.x * blockDim.x + threadIdx.x;
    if (i < n) g_cnt[i] = 0;
    if (i == 0) g_ovf_cnt = 0;
}

__device__ __forceinline__ void build_one(int s, int d) {
    int slot = atomicAdd(&g_cnt[d], 1);
    if (slot < CAP) {
        g_csr[(size_t)d * CAP + slot] = s;
    } else {
        int o = atomicAdd(&g_ovf_cnt, 1);
        if (o < OVF_CAP) g_ovf[o] = make_int2(s, d);
    }
}

// Build CSR, 8 edges/thread
__global__ void k_build8(const int* __restrict__ src,
                         const int* __restrict__ dst, int E8) {
    int t = blockIdx.x * blockDim.x + threadIdx.x;
    if (t >= E8) return;
    int4 s0 = ((const int4*)src)[2 * t];
    int4 s1 = ((const int4*)src)[2 * t + 1];
    int4 d0 = ((const int4*)dst)[2 * t];
    int4 d1 = ((const int4*)dst)[2 * t + 1];
    build_one(s0.x, d0.x); build_one(s0.y, d0.y);
    build_one(s0.z, d0.z); build_one(s0.w, d0.w);
    build_one(s1.x, d1.x); build_one(s1.y, d1.y);
    build_one(s1.z, d1.z); build_one(s1.w, d1.w);
}
__global__ void k_build1(const int* __restrict__ src,
                         const int* __restrict__ dst, int base, int E) {
    int e = base + blockIdx.x * blockDim.x + threadIdx.x;
    if (e < E) build_one(src[e], dst[e]);
}

// Per-node: isd = rsqrt(deg+1); px = isd * x
__global__ void k_node1(const float* __restrict__ x, int n) {
    int i = blockIdx.x * blockDim.x + threadIdx.x;
    if (i >= n) return;
    float isd = rsqrtf((float)(g_cnt[i] + 1));
    g_isd[i] = isd;
    g_px[i] = make_float4(isd * x[3*i+0], isd * x[3*i+1], isd * x[3*i+2], 0.f);
}

// Layer-1 pull + fused MLP. 8 lanes/node, 4 nodes/warp.
// Lane j prefetches index quads at slots [4j,4j+3] and [32+4j,32+4j+3],
// then up to 8 predicated gathers. Hidden units c=j and c=j+8 per lane.
__global__ void k_pull1(const float* __restrict__ W1,
                        const float* __restrict__ b1,
                        const float* __restrict__ W2, int n) {
    int gid  = blockIdx.x * blockDim.x + threadIdx.x;
    int lane = threadIdx.x & 31;
    int j    = lane & 7;
    int d    = gid >> 3;
    unsigned gmask = 0xFFu << (lane & 24);

    int c0 = j, c1 = j + 8;
    float w00 = __ldg(&W1[c0]),          w01 = __ldg(&W1[c1]);
    float w10 = __ldg(&W1[HID + c0]),    w11 = __ldg(&W1[HID + c1]);
    float w20 = __ldg(&W1[2*HID + c0]),  w21 = __ldg(&W1[2*HID + c1]);
    float bb0 = __ldg(&b1[c0]),          bb1 = __ldg(&b1[c1]);
    float v20 = __ldg(&W2[c0]),          v21 = __ldg(&W2[c1]);

    if (d >= n) return;
    int m = min(g_cnt[d], CAP);
    const int4* row4 = (const int4*)(g_csr + (size_t)d * CAP);

    int sA = 4 * j;          // slots sA..sA+3   (quad j)
    int sB = 32 + 4 * j;     // slots sB..sB+3   (quad j+8)
    int4 iA, iB;
    if (sA < m) iA = __ldg(&row4[j]);
    if (sB < m) iB = __ldg(&row4[j + 8]);

    float ax, ay, az;
    if (j == 0) { float4 sv = __ldg(&g_px[d]); ax = sv.x; ay = sv.y; az = sv.z; }
    else        { ax = 0.f; ay = 0.f; az = 0.f; }

    if (sA < m) {
        { float4 v = __ldg(&g_px[iA.x]); ax += v.x; ay += v.y; az += v.z; }
        if (sA + 1 < m) { float4 v = __ldg(&g_px[iA.y]); ax += v.x; ay += v.y; az += v.z; }
        if (sA + 2 < m) { float4 v = __ldg(&g_px[iA.z]); ax += v.x; ay += v.y; az += v.z; }
        if (sA + 3 < m) { float4 v = __ldg(&g_px[iA.w]); ax += v.x; ay += v.y; az += v.z; }
    }
    if (sB < m) {
        { float4 v = __ldg(&g_px[iB.x]); ax += v.x; ay += v.y; az += v.z; }
        if (sB + 1 < m) { float4 v = __ldg(&g_px[iB.y]); ax += v.x; ay += v.y; az += v.z; }
        if (sB + 2 < m) { float4 v = __ldg(&g_px[iB.z]); ax += v.x; ay += v.y; az += v.z; }
        if (sB + 3 < m) { float4 v = __ldg(&g_px[iB.w]); ax += v.x; ay += v.y; az += v.z; }
    }
    int ovn = g_ovf_cnt;
    if (ovn > 0) {
        for (int t = j; t < ovn; t += 8) {
            int2 e = g_ovf[t];
            if (e.y == d) {
                float4 v = __ldg(&g_px[e.x]);
                ax += v.x; ay += v.y; az += v.z;
            }
        }
    }
#pragma unroll
    for (int o = 4; o; o >>= 1) {
        ax += __shfl_xor_sync(gmask, ax, o);
        ay += __shfl_xor_sync(gmask, ay, o);
        az += __shfl_xor_sync(gmask, az, o);
    }
    float isd = g_isd[d];
    float f0 = isd * ax, f1 = isd * ay, f2 = isd * az;

    float h0 = fmaxf(f0 * w00 + f1 * w10 + f2 * w20 + bb0, 0.f);
    float h1 = fmaxf(f0 * w01 + f1 * w11 + f2 * w21 + bb1, 0.f);
    float ps = h0 * v20 + h1 * v21;
#pragma unroll
    for (int o = 4; o; o >>= 1) ps += __shfl_xor_sync(gmask, ps, o);
    if (j == 0) g_p[d] = isd * ps;
}

// Layer-2 pull + final. Same dual-prefetch structure, scalar gathers.
__global__ void k_pull2(const float* __restrict__ b2,
                        float* __restrict__ out, int n) {
    int gid  = blockIdx.x * blockDim.x + threadIdx.x;
    int lane = threadIdx.x & 31;
    int j    = lane & 7;
    int d    = gid >> 3;
    unsigned gmask = 0xFFu << (lane & 24);
    if (d >= n) return;
    int m = min(g_cnt[d], CAP);
    const int4* row4 = (const int4*)(g_csr + (size_t)d * CAP);

    int sA = 4 * j;
    int sB = 32 + 4 * j;
    int4 iA, iB;
    if (sA < m) iA = __ldg(&row4[j]);
    if (sB < m) iB = __ldg(&row4[j + 8]);

    float a = (j == 0) ? __ldg(&g_p[d]) : 0.f;   // self-loop
    if (sA < m) {
        a += __ldg(&g_p[iA.x]);
        if (sA + 1 < m) a += __ldg(&g_p[iA.y]);
        if (sA + 2 < m) a += __ldg(&g_p[iA.z]);
        if (sA + 3 < m) a += __ldg(&g_p[iA.w]);
    }
    if (sB < m) {
        a += __ldg(&g_p[iB.x]);
        if (sB + 1 < m) a += __ldg(&g_p[iB.y]);
        if (sB + 2 < m) a += __ldg(&g_p[iB.z]);
        if (sB + 3 < m) a += __ldg(&g_p[iB.w]);
    }
    int ovn = g_ovf_cnt;
    if (ovn > 0) {
        for (int t = j; t < ovn; t += 8) {
            int2 e = g_ovf[t];
            if (e.y == d) a += __ldg(&g_p[e.x]);
        }
    }
#pragma unroll
    for (int o = 4; o; o >>= 1) a += __shfl_xor_sync(gmask, a, o);
    if (j == 0) out[d] = __ldg(&b2[0]) + g_isd[d] * a;
}

// ---------------------------------------------------------------------------
extern "C" void kernel_launch(void* const* d_in, const int* in_sizes, int n_in,
                              void* d_out, int out_size) {
    const float* x  = (const float*)d_in[0];
    const int*   ei = (const int*)  d_in[1];
    const float* W1 = (const float*)d_in[2];
    const float* b1 = (const float*)d_in[3];
    const float* W2 = (const float*)d_in[4];
    const float* b2 = (const float*)d_in[5];
    float* out = (float*)d_out;

    int n = in_sizes[0] / 3;
    int E = in_sizes[1] / 2;
    const int* src = ei;
    const int* dst = ei + E;

    const int T = 256;
    int nb_n = (n + T - 1) / T;

    int E8   = E / 8;
    int rem  = E - E8 * 8;
    int base = E8 * 8;
    int nb_e8 = (E8 + T - 1) / T;

    long long pull_threads = 8LL * n;
    int nb_p = (int)((pull_threads + T - 1) / T);

    k_zero  <<<nb_n, T>>>(n);
    k_build8<<<nb_e8, T>>>(src, dst, E8);
    if (rem) k_build1<<<(rem + T - 1) / T, T>>>(src, dst, base, E);
    k_node1 <<<nb_n, T>>>(x, n);
    k_pull1 <<<nb_p, T>>>(W1, b1, W2, n);
    k_pull2 <<<nb_p, T>>>(b2, out, n);
}